// round 8
// baseline (speedup 1.0000x reference)
#include <cuda_runtime.h>
#include <cstdint>

#define RES   64
#define CH    8
#define NB    64
#define CORE  32
#define POS   16
#define DIMSZ (CORE*CORE*CORE*CH)   // 262144
#define BATCH 32

#define BGROUPS 8                   // 8 batch groups of 4
#define BPG     4                   // batches per thread
#define DPT     8                   // dims per thread
#define COMPUTE_BLOCKS (DIMSZ / (256 * DPT) * BGROUPS)  // 128*8 = 1024

#define F4_TOTAL  (BATCH*CH*RES*RES*RES/4)   // 16,777,216 float4
#define F4_PER_TH 8
#define ZERO_BLOCKS (F4_TOTAL / (256 * F4_PER_TH))  // 8192
#define GRID (COMPUTE_BLOCKS + ZERO_BLOCKS)

// Fused kernel:
//  blocks [0, 1024):     GEMM+scatter; 8 dims x 4 batches per thread
//                        (32 acc regs -> no spills, 3 CTAs/SM)
//  blocks [1024, 9216):  zero-fill periphery (R5-proven path, streaming stores)
__global__ void __launch_bounds__(256, 3) core_subspace_fused(
    const float* __restrict__ z,   // (32, 64)
    const float* __restrict__ U,   // (64, 262144)
    const float* __restrict__ L,   // (64,)
    const float* __restrict__ mu,  // (262144,)
    float* __restrict__ out)       // (32, 8, 64, 64, 64)
{
    const int tid = threadIdx.x;

    if (blockIdx.x >= COMPUTE_BLOCKS) {
        // ---------------- periphery zero-fill (streaming stores) -----------
        const int zb = blockIdx.x - COMPUTE_BLOCKS;
        const float4 zero4 = make_float4(0.f, 0.f, 0.f, 0.f);
        float4* o4 = reinterpret_cast<float4*>(out);
#pragma unroll
        for (int c = 0; c < F4_PER_TH; c++) {
            const int f = zb * (256 * F4_PER_TH) + c * 256 + tid;
            // f = ((((b*8+ch)*64 + i)*64) + j)*16 + w4
            const unsigned w4 = f & 15;
            const unsigned j  = (f >> 4)  & 63;
            const unsigned i  = (f >> 10) & 63;
            const bool in_core = (i - 16u < 32u) & (j - 16u < 32u) & (w4 - 4u < 8u);
            if (!in_core) __stcs(&o4[f], zero4);   // core written by compute blocks
        }
        return;
    }

    // ---------------- GEMM + scatter ----------------
    // zL packed as duplicated-f32x2 pairs; one LDS.128 broadcast feeds 8 FFMA2.
    __shared__ alignas(16) unsigned long long s_zl[BATCH * NB];  // 16 KB

    for (int idx = tid; idx < BATCH * NB; idx += 256) {
        float v = L[idx & (NB - 1)] * z[idx];
        unsigned int vb = __float_as_uint(v);
        unsigned long long p;
        asm("mov.b64 %0, {%1, %1};" : "=l"(p) : "r"(vb));
        s_zl[idx] = p;
    }
    __syncthreads();

    // Group-minor: 8 blocks sharing a dim-chunk run concurrently -> U re-reads
    // hit L2 (U = 67MB fits in 126MB L2).
    const int bg       = blockIdx.x & (BGROUPS - 1);
    const int dimchunk = blockIdx.x >> 3;            // 0..127
    const int b0       = bg * BPG;

    const int d0 = (dimchunk * 256 + tid) * DPT;     // dim index, multiple of 8

    const ulonglong2 mu_a = *reinterpret_cast<const ulonglong2*>(mu + d0);
    const ulonglong2 mu_b = *reinterpret_cast<const ulonglong2*>(mu + d0 + 4);

    unsigned long long acc[BPG][4];                  // 32 registers
#pragma unroll
    for (int b = 0; b < BPG; b++) {
        acc[b][0] = mu_a.x; acc[b][1] = mu_a.y;
        acc[b][2] = mu_b.x; acc[b][3] = mu_b.y;
    }

    const float* Up = U + d0;
    const ulonglong2* zl2 = reinterpret_cast<const ulonglong2*>(s_zl);

#define LDU(k, off) (*reinterpret_cast<const ulonglong2*>( \
                     Up + (size_t)(k) * DIMSZ + (off)))

    // Software pipeline depth 1: next kp-pair's 4 LDG.128 in flight during FMAs.
    ulonglong2 ua0 = LDU(0, 0), ua1 = LDU(0, 4);   // k = 2*kp
    ulonglong2 ub0 = LDU(1, 0), ub1 = LDU(1, 4);   // k = 2*kp+1

#pragma unroll 2
    for (int kp = 0; kp < NB / 2; kp++) {
        ulonglong2 na0, na1, nb0, nb1;
        if (kp < NB / 2 - 1) {
            na0 = LDU(2 * kp + 2, 0); na1 = LDU(2 * kp + 2, 4);
            nb0 = LDU(2 * kp + 3, 0); nb1 = LDU(2 * kp + 3, 4);
        }
#pragma unroll
        for (int b = 0; b < BPG; b++) {
            const ulonglong2 zz = zl2[(b0 + b) * (NB / 2) + kp];  // LDS.128 bcast
            asm("fma.rn.f32x2 %0, %1, %2, %0;" : "+l"(acc[b][0]) : "l"(ua0.x), "l"(zz.x));
            asm("fma.rn.f32x2 %0, %1, %2, %0;" : "+l"(acc[b][1]) : "l"(ua0.y), "l"(zz.x));
            asm("fma.rn.f32x2 %0, %1, %2, %0;" : "+l"(acc[b][2]) : "l"(ua1.x), "l"(zz.x));
            asm("fma.rn.f32x2 %0, %1, %2, %0;" : "+l"(acc[b][3]) : "l"(ua1.y), "l"(zz.x));
            asm("fma.rn.f32x2 %0, %1, %2, %0;" : "+l"(acc[b][0]) : "l"(ub0.x), "l"(zz.y));
            asm("fma.rn.f32x2 %0, %1, %2, %0;" : "+l"(acc[b][1]) : "l"(ub0.y), "l"(zz.y));
            asm("fma.rn.f32x2 %0, %1, %2, %0;" : "+l"(acc[b][2]) : "l"(ub1.x), "l"(zz.y));
            asm("fma.rn.f32x2 %0, %1, %2, %0;" : "+l"(acc[b][3]) : "l"(ub1.y), "l"(zz.y));
        }
        ua0 = na0; ua1 = na1; ub0 = nb0; ub1 = nb1;
    }
#undef LDU

    // Scatter the 8-dim chunk into the core region (streaming stores).
    // dim = ((c*32 + i)*32 + j)*32 + w ; w = d0&31 in {0,8,16,24} -> 16B aligned
    const int w = d0 & 31;
    const int j = (d0 >> 5) & 31;
    const int i = (d0 >> 10) & 31;
    const int c = d0 >> 15;

    const size_t obase = (size_t)c * (RES * RES * RES)
                       + (size_t)(i + POS) * (RES * RES)
                       + (size_t)(j + POS) * RES
                       + (size_t)(w + POS);

#pragma unroll
    for (int b = 0; b < BPG; b++) {
        float* o = out + (size_t)(b0 + b) * (CH * RES * RES * RES) + obase;
        float4 v0, v1;
        v0.x = __uint_as_float((unsigned)(acc[b][0]));
        v0.y = __uint_as_float((unsigned)(acc[b][0] >> 32));
        v0.z = __uint_as_float((unsigned)(acc[b][1]));
        v0.w = __uint_as_float((unsigned)(acc[b][1] >> 32));
        v1.x = __uint_as_float((unsigned)(acc[b][2]));
        v1.y = __uint_as_float((unsigned)(acc[b][2] >> 32));
        v1.z = __uint_as_float((unsigned)(acc[b][3]));
        v1.w = __uint_as_float((unsigned)(acc[b][3] >> 32));
        __stcs(reinterpret_cast<float4*>(o),     v0);
        __stcs(reinterpret_cast<float4*>(o + 4), v1);
    }
}

extern "C" void kernel_launch(void* const* d_in, const int* in_sizes, int n_in,
                              void* d_out, int out_size)
{
    const float* z  = (const float*)d_in[0];
    const float* U  = (const float*)d_in[1];
    const float* L  = (const float*)d_in[2];
    const float* mu = (const float*)d_in[3];
    float* out = (float*)d_out;

    core_subspace_fused<<<GRID, 256>>>(z, U, L, mu, out);
}

// round 9
// speedup vs baseline: 1.2319x; 1.2319x over previous
#include <cuda_runtime.h>
#include <cstdint>

#define RES   64
#define CH    8
#define NB    64
#define CORE  32
#define POS   16
#define DIMSZ (CORE*CORE*CORE*CH)   // 262144
#define BATCH 32

#define BGROUPS 4                   // 4 batch groups of 8
#define BPG     8                   // batches per thread
#define DPT     8                   // dims per thread
#define NBLK    512                 // 512*256 threads; every block: GEMM + zeros

#define F4_TOTAL (BATCH*CH*RES*RES*RES/4)   // 16,777,216 float4
#define ZPT      128                // zero float4 per thread (4 per kp iter)
#define ZSTRIDE  131072             // = NBLK*256 float4 (2^17) stride per store

// Uniform fused blocks: each thread computes an 8-dim x 8-batch GEMM tile AND
// streams 128 periphery-zero float4 stores interleaved into the k loop, so
// every SM keeps the LSU/DRAM write stream busy during FMA/LDG latency.
__global__ void __launch_bounds__(256, 2) core_subspace_fused(
    const float* __restrict__ z,   // (32, 64)
    const float* __restrict__ U,   // (64, 262144)
    const float* __restrict__ L,   // (64,)
    const float* __restrict__ mu,  // (262144,)
    float* __restrict__ out)       // (32, 8, 64, 64, 64)
{
    const int tid = threadIdx.x;
    const int bid = blockIdx.x;

    // ---- zero-store setup: predicate + coords depend only on f0 (stride 2^17
    //      keeps low 16 bits fixed: i, j, w4 constant across all 128 stores) ----
    const int f0 = bid * 256 + tid;                  // 0..131071
    {
        // nothing
    }
    const unsigned zw4 = f0 & 15;
    const unsigned zj  = (f0 >> 4)  & 63;
    const unsigned zi  = (f0 >> 10) & 63;
    const bool zskip = (zi - 16u < 32u) & (zj - 16u < 32u) & (zw4 - 4u < 8u);
    float4* const zp = reinterpret_cast<float4*>(out) + f0;
    const float4 zero4 = make_float4(0.f, 0.f, 0.f, 0.f);

    // ---- zL: packed duplicated-f32x2 pairs; one LDS.128 bcast feeds 8 FFMA2 ----
    __shared__ alignas(16) unsigned long long s_zl[BATCH * NB];  // 16 KB

    for (int idx = tid; idx < BATCH * NB; idx += 256) {
        float v = L[idx & (NB - 1)] * z[idx];
        unsigned int vb = __float_as_uint(v);
        unsigned long long p;
        asm("mov.b64 %0, {%1, %1};" : "=l"(p) : "r"(vb));
        s_zl[idx] = p;
    }
    __syncthreads();

    // Group-minor mapping (R5): 4 blocks sharing a dim-chunk run concurrently.
    const int bg       = bid & (BGROUPS - 1);
    const int dimchunk = bid >> 2;                   // 0..127
    const int b0       = bg * BPG;

    const int d0 = (dimchunk * 256 + tid) * DPT;     // dim index, multiple of 8

    const ulonglong2 mu_a = *reinterpret_cast<const ulonglong2*>(mu + d0);
    const ulonglong2 mu_b = *reinterpret_cast<const ulonglong2*>(mu + d0 + 4);

    unsigned long long acc[BPG][4];                  // 64 registers
#pragma unroll
    for (int b = 0; b < BPG; b++) {
        acc[b][0] = mu_a.x; acc[b][1] = mu_a.y;
        acc[b][2] = mu_b.x; acc[b][3] = mu_b.y;
    }

    const float* Up = U + d0;
    const ulonglong2* zl2 = reinterpret_cast<const ulonglong2*>(s_zl);

#define LDU(k, off) (*reinterpret_cast<const ulonglong2*>( \
                     Up + (size_t)(k) * DIMSZ + (off)))

    // Software pipeline depth 1.
    ulonglong2 ua0 = LDU(0, 0), ua1 = LDU(0, 4);   // k = 2*kp
    ulonglong2 ub0 = LDU(1, 0), ub1 = LDU(1, 4);   // k = 2*kp+1

    for (int kp = 0; kp < NB / 2; kp++) {
        ulonglong2 na0, na1, nb0, nb1;
        if (kp < NB / 2 - 1) {
            na0 = LDU(2 * kp + 2, 0); na1 = LDU(2 * kp + 2, 4);
            nb0 = LDU(2 * kp + 3, 0); nb1 = LDU(2 * kp + 3, 4);
        }

        // 4 periphery zero stores per iteration, issued while LDGs are in
        // flight: 1 IADD + 1 STG each, no per-store decode.
        if (!zskip) {
#pragma unroll
            for (int c = 0; c < 4; c++)
                __stcs(zp + ((size_t)(4 * kp + c) << 17), zero4);
        }

#pragma unroll
        for (int b = 0; b < BPG; b++) {
            const ulonglong2 zz = zl2[(b0 + b) * (NB / 2) + kp];  // LDS.128 bcast
            asm("fma.rn.f32x2 %0, %1, %2, %0;" : "+l"(acc[b][0]) : "l"(ua0.x), "l"(zz.x));
            asm("fma.rn.f32x2 %0, %1, %2, %0;" : "+l"(acc[b][1]) : "l"(ua0.y), "l"(zz.x));
            asm("fma.rn.f32x2 %0, %1, %2, %0;" : "+l"(acc[b][2]) : "l"(ua1.x), "l"(zz.x));
            asm("fma.rn.f32x2 %0, %1, %2, %0;" : "+l"(acc[b][3]) : "l"(ua1.y), "l"(zz.x));
            asm("fma.rn.f32x2 %0, %1, %2, %0;" : "+l"(acc[b][0]) : "l"(ub0.x), "l"(zz.y));
            asm("fma.rn.f32x2 %0, %1, %2, %0;" : "+l"(acc[b][1]) : "l"(ub0.y), "l"(zz.y));
            asm("fma.rn.f32x2 %0, %1, %2, %0;" : "+l"(acc[b][2]) : "l"(ub1.x), "l"(zz.y));
            asm("fma.rn.f32x2 %0, %1, %2, %0;" : "+l"(acc[b][3]) : "l"(ub1.y), "l"(zz.y));
        }
        ua0 = na0; ua1 = na1; ub0 = nb0; ub1 = nb1;
    }
#undef LDU

    // Scatter the 8-dim chunk into the core region (streaming stores).
    // dim = ((c*32 + i)*32 + j)*32 + w ; w = d0&31 in {0,8,16,24} -> 16B aligned
    const int w = d0 & 31;
    const int j = (d0 >> 5) & 31;
    const int i = (d0 >> 10) & 31;
    const int c = d0 >> 15;

    const size_t obase = (size_t)c * (RES * RES * RES)
                       + (size_t)(i + POS) * (RES * RES)
                       + (size_t)(j + POS) * RES
                       + (size_t)(w + POS);

#pragma unroll
    for (int b = 0; b < BPG; b++) {
        float* o = out + (size_t)(b0 + b) * (CH * RES * RES * RES) + obase;
        float4 v0, v1;
        v0.x = __uint_as_float((unsigned)(acc[b][0]));
        v0.y = __uint_as_float((unsigned)(acc[b][0] >> 32));
        v0.z = __uint_as_float((unsigned)(acc[b][1]));
        v0.w = __uint_as_float((unsigned)(acc[b][1] >> 32));
        v1.x = __uint_as_float((unsigned)(acc[b][2]));
        v1.y = __uint_as_float((unsigned)(acc[b][2] >> 32));
        v1.z = __uint_as_float((unsigned)(acc[b][3]));
        v1.w = __uint_as_float((unsigned)(acc[b][3] >> 32));
        __stcs(reinterpret_cast<float4*>(o),     v0);
        __stcs(reinterpret_cast<float4*>(o + 4), v1);
    }
}

extern "C" void kernel_launch(void* const* d_in, const int* in_sizes, int n_in,
                              void* d_out, int out_size)
{
    const float* z  = (const float*)d_in[0];
    const float* U  = (const float*)d_in[1];
    const float* L  = (const float*)d_in[2];
    const float* mu = (const float*)d_in[3];
    float* out = (float*)d_out;

    core_subspace_fused<<<NBLK, 256>>>(z, U, L, mu, out);
}

// round 10
// speedup vs baseline: 1.3329x; 1.0820x over previous
#include <cuda_runtime.h>
#include <cstdint>

#define RES   64
#define CH    8
#define NB    64
#define CORE  32
#define POS   16
#define DIMSZ (CORE*CORE*CORE*CH)   // 262144
#define BATCH 32

#define BGROUPS 4                   // 4 batch groups of 8
#define BPG     8                   // batches per thread
#define DPT     8                   // dims per thread
#define CBLK (DIMSZ / (256 * DPT) * BGROUPS)   // 512 compute blocks

#define F4_TOTAL  (BATCH*CH*RES*RES*RES/4)     // 16,777,216 float4
#define F4_PER_TH 8
#define ZBLK (F4_TOTAL / (256 * F4_PER_TH))    // 8192 zero blocks

// ---------------------------------------------------------------------------
// Kernel 1: periphery zero-fill. Tiny register footprint, high occupancy,
// pure streaming stores. Runs CONCURRENTLY with the GEMM kernel (parallel
// graph branch) and fills SM gaps the fat GEMM CTAs leave.
// ---------------------------------------------------------------------------
__global__ void __launch_bounds__(256, 8) zero_periphery(float* __restrict__ out)
{
    const int tid = threadIdx.x;
    const int zb  = blockIdx.x;
    const float4 zero4 = make_float4(0.f, 0.f, 0.f, 0.f);
    float4* o4 = reinterpret_cast<float4*>(out);
#pragma unroll
    for (int c = 0; c < F4_PER_TH; c++) {
        const int f = zb * (256 * F4_PER_TH) + c * 256 + tid;
        // f = ((((b*8+ch)*64 + i)*64) + j)*16 + w4
        const unsigned w4 = f & 15;
        const unsigned j  = (f >> 4)  & 63;
        const unsigned i  = (f >> 10) & 63;
        const bool in_core = (i - 16u < 32u) & (j - 16u < 32u) & (w4 - 4u < 8u);
        if (!in_core) __stcs(&o4[f], zero4);   // core written by GEMM kernel
    }
}

// ---------------------------------------------------------------------------
// Kernel 2: (L*z)@U + mu scattered into the core. R5-proven structure:
// 8 dims x 8 batches per thread, group-minor so U re-reads hit L2,
// depth-1 LDG pipeline, LDS.128 zL broadcast feeding 8 FFMA2 each.
// ---------------------------------------------------------------------------
__global__ void __launch_bounds__(256, 2) core_gemm(
    const float* __restrict__ z,   // (32, 64)
    const float* __restrict__ U,   // (64, 262144)
    const float* __restrict__ L,   // (64,)
    const float* __restrict__ mu,  // (262144,)
    float* __restrict__ out)       // (32, 8, 64, 64, 64)
{
    const int tid = threadIdx.x;

    __shared__ alignas(16) unsigned long long s_zl[BATCH * NB];  // 16 KB

    for (int idx = tid; idx < BATCH * NB; idx += 256) {
        float v = L[idx & (NB - 1)] * z[idx];
        unsigned int vb = __float_as_uint(v);
        unsigned long long p;
        asm("mov.b64 %0, {%1, %1};" : "=l"(p) : "r"(vb));
        s_zl[idx] = p;
    }
    __syncthreads();

    const int bg       = blockIdx.x & (BGROUPS - 1);
    const int dimchunk = blockIdx.x >> 2;            // 0..127
    const int b0       = bg * BPG;

    const int d0 = (dimchunk * 256 + tid) * DPT;     // dim index, multiple of 8

    const ulonglong2 mu_a = *reinterpret_cast<const ulonglong2*>(mu + d0);
    const ulonglong2 mu_b = *reinterpret_cast<const ulonglong2*>(mu + d0 + 4);

    unsigned long long acc[BPG][4];                  // 64 registers
#pragma unroll
    for (int b = 0; b < BPG; b++) {
        acc[b][0] = mu_a.x; acc[b][1] = mu_a.y;
        acc[b][2] = mu_b.x; acc[b][3] = mu_b.y;
    }

    const float* Up = U + d0;
    const ulonglong2* zl2 = reinterpret_cast<const ulonglong2*>(s_zl);

#define LDU(k, off) (*reinterpret_cast<const ulonglong2*>( \
                     Up + (size_t)(k) * DIMSZ + (off)))

    ulonglong2 ua0 = LDU(0, 0), ua1 = LDU(0, 4);   // k = 2*kp
    ulonglong2 ub0 = LDU(1, 0), ub1 = LDU(1, 4);   // k = 2*kp+1

#pragma unroll 2
    for (int kp = 0; kp < NB / 2; kp++) {
        ulonglong2 na0, na1, nb0, nb1;
        if (kp < NB / 2 - 1) {
            na0 = LDU(2 * kp + 2, 0); na1 = LDU(2 * kp + 2, 4);
            nb0 = LDU(2 * kp + 3, 0); nb1 = LDU(2 * kp + 3, 4);
        }
#pragma unroll
        for (int b = 0; b < BPG; b++) {
            const ulonglong2 zz = zl2[(b0 + b) * (NB / 2) + kp];  // LDS.128 bcast
            asm("fma.rn.f32x2 %0, %1, %2, %0;" : "+l"(acc[b][0]) : "l"(ua0.x), "l"(zz.x));
            asm("fma.rn.f32x2 %0, %1, %2, %0;" : "+l"(acc[b][1]) : "l"(ua0.y), "l"(zz.x));
            asm("fma.rn.f32x2 %0, %1, %2, %0;" : "+l"(acc[b][2]) : "l"(ua1.x), "l"(zz.x));
            asm("fma.rn.f32x2 %0, %1, %2, %0;" : "+l"(acc[b][3]) : "l"(ua1.y), "l"(zz.x));
            asm("fma.rn.f32x2 %0, %1, %2, %0;" : "+l"(acc[b][0]) : "l"(ub0.x), "l"(zz.y));
            asm("fma.rn.f32x2 %0, %1, %2, %0;" : "+l"(acc[b][1]) : "l"(ub0.y), "l"(zz.y));
            asm("fma.rn.f32x2 %0, %1, %2, %0;" : "+l"(acc[b][2]) : "l"(ub1.x), "l"(zz.y));
            asm("fma.rn.f32x2 %0, %1, %2, %0;" : "+l"(acc[b][3]) : "l"(ub1.y), "l"(zz.y));
        }
        ua0 = na0; ua1 = na1; ub0 = nb0; ub1 = nb1;
    }
#undef LDU

    // Scatter the 8-dim chunk into the core region (streaming stores).
    const int w = d0 & 31;
    const int j = (d0 >> 5) & 31;
    const int i = (d0 >> 10) & 31;
    const int c = d0 >> 15;

    const size_t obase = (size_t)c * (RES * RES * RES)
                       + (size_t)(i + POS) * (RES * RES)
                       + (size_t)(j + POS) * RES
                       + (size_t)(w + POS);

#pragma unroll
    for (int b = 0; b < BPG; b++) {
        float* o = out + (size_t)(b0 + b) * (CH * RES * RES * RES) + obase;
        float4 v0, v1;
        v0.x = __uint_as_float((unsigned)(acc[b][0]));
        v0.y = __uint_as_float((unsigned)(acc[b][0] >> 32));
        v0.z = __uint_as_float((unsigned)(acc[b][1]));
        v0.w = __uint_as_float((unsigned)(acc[b][1] >> 32));
        v1.x = __uint_as_float((unsigned)(acc[b][2]));
        v1.y = __uint_as_float((unsigned)(acc[b][2] >> 32));
        v1.z = __uint_as_float((unsigned)(acc[b][3]));
        v1.w = __uint_as_float((unsigned)(acc[b][3] >> 32));
        __stcs(reinterpret_cast<float4*>(o),     v0);
        __stcs(reinterpret_cast<float4*>(o + 4), v1);
    }
}

// ---------------------------------------------------------------------------
// Launcher: fork-join stream capture so the two kernels become PARALLEL graph
// nodes (they write disjoint regions; no ordering needed between them).
// Stream/events are host-side handles created once — no device allocation.
// ---------------------------------------------------------------------------
static cudaStream_t g_s2 = nullptr;
static cudaEvent_t  g_evFork = nullptr, g_evJoin = nullptr;

extern "C" void kernel_launch(void* const* d_in, const int* in_sizes, int n_in,
                              void* d_out, int out_size)
{
    const float* z  = (const float*)d_in[0];
    const float* U  = (const float*)d_in[1];
    const float* L  = (const float*)d_in[2];
    const float* mu = (const float*)d_in[3];
    float* out = (float*)d_out;

    if (g_s2 == nullptr) {
        cudaStreamCreateWithFlags(&g_s2, cudaStreamNonBlocking);
        cudaEventCreateWithFlags(&g_evFork, cudaEventDisableTiming);
        cudaEventCreateWithFlags(&g_evJoin, cudaEventDisableTiming);
    }

    // Fork: second stream joins the capture as a parallel branch.
    cudaEventRecord(g_evFork, 0);
    cudaStreamWaitEvent(g_s2, g_evFork, 0);

    core_gemm<<<CBLK, 256, 0, g_s2>>>(z, U, L, mu, out);   // parallel branch
    zero_periphery<<<ZBLK, 256, 0, 0>>>(out);              // capture stream

    // Join: capture stream waits on the branch.
    cudaEventRecord(g_evJoin, g_s2);
    cudaStreamWaitEvent(0, g_evJoin, 0);
}

// round 11
// speedup vs baseline: 1.3347x; 1.0013x over previous
#include <cuda_runtime.h>
#include <cstdint>

#define RES   64
#define CH    8
#define NB    64
#define CORE  32
#define POS   16
#define DIMSZ (CORE*CORE*CORE*CH)   // 262144
#define BATCH 32

// ---- GEMM kernel geometry ----
#define DPB   256                          // dims per block
#define CBLK  (DIMSZ / DPB)                // 1024 compute blocks
#define SMEM_U_BYTES (DPB * NB * 4)        // 64 KB U tile
#define SMEM_Z_BYTES (NB * BATCH * 8)      // 16 KB packed zL
#define SMEM_TOTAL   (SMEM_U_BYTES + SMEM_Z_BYTES)   // 80 KB dynamic

// ---- zero kernel geometry (R10-proven) ----
#define F4_TOTAL  (BATCH*CH*RES*RES*RES/4) // 16,777,216 float4
#define F4_PER_TH 8
#define ZBLK (F4_TOTAL / (256 * F4_PER_TH))  // 8192

// ---------------------------------------------------------------------------
// Kernel 1: periphery zero-fill (parallel graph branch, proven 34.7us).
// ---------------------------------------------------------------------------
__global__ void __launch_bounds__(256, 8) zero_periphery(float* __restrict__ out)
{
    const int tid = threadIdx.x;
    const int zb  = blockIdx.x;
    const float4 zero4 = make_float4(0.f, 0.f, 0.f, 0.f);
    float4* o4 = reinterpret_cast<float4*>(out);
#pragma unroll
    for (int c = 0; c < F4_PER_TH; c++) {
        const int f = zb * (256 * F4_PER_TH) + c * 256 + tid;
        const unsigned w4 = f & 15;
        const unsigned j  = (f >> 4)  & 63;
        const unsigned i  = (f >> 10) & 63;
        const bool in_core = (i - 16u < 32u) & (j - 16u < 32u) & (w4 - 4u < 8u);
        if (!in_core) __stcs(&o4[f], zero4);   // core written by GEMM kernel
    }
}

// ---------------------------------------------------------------------------
// Kernel 2: U staged ONCE into a 64KB smem tile per 256-dim block slice; all
// 32 batches consumed from the tile (4 batch-groups x 64 dim-quads = 256 thr).
// Each thread: 4 dims x 8 batches, acc = 16 u64 = 32 regs. Inner loop is pure
// smem: 1 LDS.128 (u) + 4 LDS.128 bcast (zL) -> 16 FFMA2.
// ---------------------------------------------------------------------------
#define FMA2(a, u, s) asm("fma.rn.f32x2 %0, %1, %2, %0;" : "+l"(a) : "l"(u), "l"(s))

__global__ void __launch_bounds__(256, 2) core_gemm(
    const float* __restrict__ z,   // (32, 64)
    const float* __restrict__ U,   // (64, 262144)
    const float* __restrict__ L,   // (64,)
    const float* __restrict__ mu,  // (262144,)
    float* __restrict__ out)       // (32, 8, 64, 64, 64)
{
    extern __shared__ char smem[];
    float* su = reinterpret_cast<float*>(smem);                      // [NB][DPB]
    unsigned long long* szb =
        reinterpret_cast<unsigned long long*>(smem + SMEM_U_BYTES);  // [NB][BATCH]

    const int tid = threadIdx.x;
    const int D0  = blockIdx.x * DPB;

    // zL packed duplicated-f32x2, layout [k][batch] so 8 batches = 4 LDS.128.
    for (int idx = tid; idx < NB * BATCH; idx += 256) {
        const int b = idx & 31;
        const int k = idx >> 5;
        float v = L[k] * z[b * NB + k];
        unsigned int vb = __float_as_uint(v);
        unsigned long long p;
        asm("mov.b64 %0, {%1, %1};" : "=l"(p) : "r"(vb));
        szb[k * BATCH + b] = p;
    }

    // Stage U tile: 64 rows x 256 floats = 4096 float4, 16 per thread.
#pragma unroll
    for (int i = 0; i < 16; i++) {
        const int idx = i * 256 + tid;
        const int k   = idx >> 6;        // row
        const int c4  = idx & 63;        // float4 within row
        const float4 v = *reinterpret_cast<const float4*>(
            U + (size_t)k * DIMSZ + D0 + c4 * 4);
        *reinterpret_cast<float4*>(&su[k * DPB + c4 * 4]) = v;
    }
    __syncthreads();

    const int g  = tid >> 6;         // batch group 0..3 (8 batches each)
    const int q  = tid & 63;         // dim-quad 0..63
    const int b0 = g * 8;
    const int d0 = D0 + q * 4;

    const ulonglong2 mu2 = *reinterpret_cast<const ulonglong2*>(mu + d0);

    unsigned long long acc[8][2];    // 32 registers
#pragma unroll
    for (int bb = 0; bb < 8; bb++) { acc[bb][0] = mu2.x; acc[bb][1] = mu2.y; }

#pragma unroll 4
    for (int k = 0; k < NB; k++) {
        const ulonglong2 ud = *reinterpret_cast<const ulonglong2*>(
            &su[k * DPB + q * 4]);                       // LDS.128, conflict-free
        const ulonglong2* zp = reinterpret_cast<const ulonglong2*>(
            &szb[k * BATCH + b0]);                       // 16B aligned
        const ulonglong2 z01 = zp[0];                    // LDS.128 broadcast x4
        const ulonglong2 z23 = zp[1];
        const ulonglong2 z45 = zp[2];
        const ulonglong2 z67 = zp[3];

        FMA2(acc[0][0], ud.x, z01.x); FMA2(acc[0][1], ud.y, z01.x);
        FMA2(acc[1][0], ud.x, z01.y); FMA2(acc[1][1], ud.y, z01.y);
        FMA2(acc[2][0], ud.x, z23.x); FMA2(acc[2][1], ud.y, z23.x);
        FMA2(acc[3][0], ud.x, z23.y); FMA2(acc[3][1], ud.y, z23.y);
        FMA2(acc[4][0], ud.x, z45.x); FMA2(acc[4][1], ud.y, z45.x);
        FMA2(acc[5][0], ud.x, z45.y); FMA2(acc[5][1], ud.y, z45.y);
        FMA2(acc[6][0], ud.x, z67.x); FMA2(acc[6][1], ud.y, z67.x);
        FMA2(acc[7][0], ud.x, z67.y); FMA2(acc[7][1], ud.y, z67.y);
    }

    // Scatter 4-dim chunk into the core for this thread's 8 batches.
    // dim = ((c*32 + i)*32 + j)*32 + w ; w = d0&31 multiple of 4 -> 16B aligned
    const int w = d0 & 31;
    const int j = (d0 >> 5) & 31;
    const int i = (d0 >> 10) & 31;
    const int c = d0 >> 15;

    const size_t obase = (size_t)c * (RES * RES * RES)
                       + (size_t)(i + POS) * (RES * RES)
                       + (size_t)(j + POS) * RES
                       + (size_t)(w + POS);

#pragma unroll
    for (int bb = 0; bb < 8; bb++) {
        float* o = out + (size_t)(b0 + bb) * (CH * RES * RES * RES) + obase;
        float4 v;
        v.x = __uint_as_float((unsigned)(acc[bb][0]));
        v.y = __uint_as_float((unsigned)(acc[bb][0] >> 32));
        v.z = __uint_as_float((unsigned)(acc[bb][1]));
        v.w = __uint_as_float((unsigned)(acc[bb][1] >> 32));
        __stcs(reinterpret_cast<float4*>(o), v);
    }
}

// ---------------------------------------------------------------------------
// Launcher: fork-join stream capture -> two PARALLEL graph nodes.
// ---------------------------------------------------------------------------
static cudaStream_t g_s2 = nullptr;
static cudaEvent_t  g_evFork = nullptr, g_evJoin = nullptr;

extern "C" void kernel_launch(void* const* d_in, const int* in_sizes, int n_in,
                              void* d_out, int out_size)
{
    const float* z  = (const float*)d_in[0];
    const float* U  = (const float*)d_in[1];
    const float* L  = (const float*)d_in[2];
    const float* mu = (const float*)d_in[3];
    float* out = (float*)d_out;

    if (g_s2 == nullptr) {
        cudaStreamCreateWithFlags(&g_s2, cudaStreamNonBlocking);
        cudaEventCreateWithFlags(&g_evFork, cudaEventDisableTiming);
        cudaEventCreateWithFlags(&g_evJoin, cudaEventDisableTiming);
    }
    // Host-side attribute set (idempotent, not a stream op).
    cudaFuncSetAttribute(core_gemm,
                         cudaFuncAttributeMaxDynamicSharedMemorySize, SMEM_TOTAL);

    // Fork: second stream joins the capture as a parallel branch.
    cudaEventRecord(g_evFork, 0);
    cudaStreamWaitEvent(g_s2, g_evFork, 0);

    core_gemm<<<CBLK, 256, SMEM_TOTAL, g_s2>>>(z, U, L, mu, out);  // branch
    zero_periphery<<<ZBLK, 256, 0, 0>>>(out);                      // capture stream

    // Join.
    cudaEventRecord(g_evJoin, g_s2);
    cudaStreamWaitEvent(0, g_evJoin, 0);
}